// round 2
// baseline (speedup 1.0000x reference)
#include <cuda_runtime.h>

// ---------------------------------------------------------------------------
// PromptedAttention: B=8, H=W=32, C=768, heads=12, hd=64, nt=8, N=1032
// Round 0: fp32 SIMT baseline, flash-style fused attention.
// ---------------------------------------------------------------------------

#define BATCH     8
#define HEADS     12
#define HD        64
#define C_DIM     768
#define NT        8
#define HW        1024
#define NSEQ      1032            // NT + HW
#define BHN       96              // BATCH*HEADS
#define MROWS     8256            // BATCH*NSEQ
#define QKV_N     2304
#define XOUT_ELEMS 6291456        // 8*32*32*768

// scratch (device globals: the only legal scratch under the alloc guards)
__device__ float g_q[BHN * NSEQ * HD];
__device__ float g_k[BHN * NSEQ * HD];
__device__ float g_v[BHN * NSEQ * HD];
__device__ float g_relh[BHN * 32 * 32 * 32];
__device__ float g_relw[BHN * 32 * 32 * 32];
__device__ float g_ctx[MROWS * C_DIM];

// ---------------------------------------------------------------------------
// K1: fused concat + QKV GEMM.  A = xs (8256 x 768, gathered rows),
// B = qkv_w (768 x 2304).  Epilogue scatters into g_q/g_k/g_v with
// (b*12+head, n, d) layout.  128x128 tile, BK=8, 8x8 microtile, 256 threads.
// ---------------------------------------------------------------------------
__global__ __launch_bounds__(256) void qkv_gemm_kernel(
    const float* __restrict__ x, const float* __restrict__ vp,
    const float* __restrict__ W, const float* __restrict__ bias)
{
    __shared__ float As[8][128];
    __shared__ float Bs[8][128];

    const int m0 = blockIdx.y * 128;
    const int n0 = blockIdx.x * 128;
    const int tid = threadIdx.x;
    const int tx = tid & 15, ty = tid >> 4;

    // A loader: thread -> (row, k-quad)
    const int aRow = tid >> 1;
    const int aK4  = (tid & 1) * 4;
    const int am   = m0 + aRow;
    const bool avalid = (am < MROWS);
    const float* arp;
    {
        int mm = avalid ? am : 0;
        int b = mm / NSEQ, n = mm % NSEQ;
        arp = (n < NT) ? (vp + ((size_t)b * NT + n) * C_DIM)
                       : (x  + ((size_t)b * HW + (n - NT)) * C_DIM);
    }
    // B loader
    const int bK = tid >> 5;
    const int bN = (tid & 31) * 4;

    float acc[8][8];
#pragma unroll
    for (int i = 0; i < 8; ++i)
#pragma unroll
        for (int j = 0; j < 8; ++j) acc[i][j] = 0.f;

    for (int k0 = 0; k0 < C_DIM; k0 += 8) {
        float4 av = avalid ? *(const float4*)(arp + k0 + aK4)
                           : make_float4(0.f, 0.f, 0.f, 0.f);
        As[aK4 + 0][aRow] = av.x;
        As[aK4 + 1][aRow] = av.y;
        As[aK4 + 2][aRow] = av.z;
        As[aK4 + 3][aRow] = av.w;
        *(float4*)&Bs[bK][bN] =
            *(const float4*)(W + (size_t)(k0 + bK) * QKV_N + n0 + bN);
        __syncthreads();
#pragma unroll
        for (int k = 0; k < 8; ++k) {
            float a[8], bb[8];
            *(float4*)&a[0]  = *(float4*)&As[k][ty * 8];
            *(float4*)&a[4]  = *(float4*)&As[k][ty * 8 + 4];
            *(float4*)&bb[0] = *(float4*)&Bs[k][tx * 8];
            *(float4*)&bb[4] = *(float4*)&Bs[k][tx * 8 + 4];
#pragma unroll
            for (int i = 0; i < 8; ++i)
#pragma unroll
                for (int j = 0; j < 8; ++j) acc[i][j] += a[i] * bb[j];
        }
        __syncthreads();
    }

    // Epilogue: 8 consecutive output columns per thread -> same (which, head),
    // consecutive d -> vectorized scatter.
    float* bufs[3] = {g_q, g_k, g_v};
    const int ncol = n0 + tx * 8;
    const int which = ncol / C_DIM;
    const int c2 = ncol % C_DIM;
    const int head = c2 >> 6;
    const int dbase = c2 & 63;
    float* buf = bufs[which];
    float bb8[8];
#pragma unroll
    for (int j = 0; j < 8; ++j) bb8[j] = bias[ncol + j];

#pragma unroll
    for (int i = 0; i < 8; ++i) {
        int m = m0 + ty * 8 + i;
        if (m >= MROWS) continue;
        int b = m / NSEQ, nn = m % NSEQ;
        size_t mo = (size_t)b * (HEADS * NSEQ * HD) + (size_t)nn * HD;
        float* dst = buf + mo + (size_t)head * (NSEQ * HD) + dbase;
        float4 v0, v1;
        v0.x = acc[i][0] + bb8[0]; v0.y = acc[i][1] + bb8[1];
        v0.z = acc[i][2] + bb8[2]; v0.w = acc[i][3] + bb8[3];
        v1.x = acc[i][4] + bb8[4]; v1.y = acc[i][5] + bb8[5];
        v1.z = acc[i][6] + bb8[6]; v1.w = acc[i][7] + bb8[7];
        *(float4*)dst = v0;
        *(float4*)(dst + 4) = v1;
    }
}

// ---------------------------------------------------------------------------
// K2: rel_h / rel_w bias GEMMs.
// variant 0: block (h, bh): out[w][k] = sum_c q[bh, pix(h,w), c] * Rh[h-k+31, c]
// variant 1: block (w, bh): out[h][k] = sum_c q[bh, pix(h,w), c] * Rw[w-k+31, c]
// ---------------------------------------------------------------------------
__global__ __launch_bounds__(256) void rel_kernel(
    const float* __restrict__ rph, const float* __restrict__ rpw)
{
    __shared__ float qs[32 * 64];
    __shared__ float RsT[64 * 33];

    const int bh = blockIdx.y;
    const int idx0 = blockIdx.x;        // h (variant 0) or w (variant 1)
    const int variant = blockIdx.z;
    const int tid = threadIdx.x;

#pragma unroll
    for (int it = 0; it < 8; ++it) {
        int idx = tid + it * 256;       // 2048
        int r = idx >> 6, c = idx & 63;
        int n = (variant == 0) ? (NT + idx0 * 32 + r) : (NT + r * 32 + idx0);
        qs[idx] = g_q[((size_t)bh * NSEQ + n) * HD + c];
    }
    const float* rp = (variant == 0) ? rph : rpw;
#pragma unroll
    for (int it = 0; it < 8; ++it) {
        int idx = tid + it * 256;
        int k = idx >> 6, c = idx & 63;
        RsT[c * 33 + k] = rp[(size_t)(idx0 - k + 31) * HD + c];
    }
    __syncthreads();

    const int ty = tid >> 3;            // output row 0..31
    const int txk = tid & 7;            // k-group
    float acc[4] = {0.f, 0.f, 0.f, 0.f};
#pragma unroll 8
    for (int c = 0; c < 64; ++c) {
        float q = qs[ty * 64 + c];
#pragma unroll
        for (int j = 0; j < 4; ++j) acc[j] += q * RsT[c * 33 + txk * 4 + j];
    }
    float* outb = (variant == 0) ? g_relh : g_relw;
    size_t base = (variant == 0)
        ? ((((size_t)bh * 32 + idx0) * 32 + ty) * 32)
        : ((((size_t)bh * 32 + ty) * 32 + idx0) * 32);
#pragma unroll
    for (int j = 0; j < 4; ++j) outb[base + txk * 4 + j] = acc[j];
}

// ---------------------------------------------------------------------------
// K3: flash attention.  Block = (q-tile of 64, bh).  Online softmax over 17
// key tiles of 64.  Bias decomposed: relh[q][hj] + relw[q][wj] from smem rows.
// ---------------------------------------------------------------------------
#define ATTN_SMEM_FLOATS (64*65 + 64*65 + 64*64 + 64*68 + 64*32 + 64*32 + 3*64)
#define ATTN_SMEM_BYTES  (ATTN_SMEM_FLOATS * 4)

__global__ __launch_bounds__(256) void attn_kernel()
{
    extern __shared__ float sm[];
    float* qsT  = sm;                   // [64 d][65]
    float* ksT  = qsT + 64 * 65;        // [64 d][65]
    float* vs   = ksT + 64 * 65;        // [64 k][64 d]
    float* ps   = vs + 64 * 64;         // [64 q][68]
    float* rhs  = ps + 64 * 68;         // [64 q][32]
    float* rws  = rhs + 64 * 32;        // [64 q][32]
    float* rowm = rws + 64 * 32;
    float* rowl = rowm + 64;
    float* rowsc = rowl + 64;

    const int tid = threadIdx.x;
    const int bh = blockIdx.y;
    const int b = bh / HEADS, head = bh % HEADS;
    const int q0 = blockIdx.x * 64;
    const int tx = tid & 15, ty = tid >> 4;

    const float* qbase = g_q + (size_t)bh * NSEQ * HD;
    const float* kbase = g_k + (size_t)bh * NSEQ * HD;
    const float* vbase = g_v + (size_t)bh * NSEQ * HD;

    // Q tile, transposed + prescaled (scale only in attn scores, not rel bias)
#pragma unroll
    for (int it = 0; it < 16; ++it) {
        int idx = tid + it * 256;
        int r = idx >> 6, d = idx & 63;
        int qg = q0 + r;
        float v = (qg < NSEQ) ? qbase[(size_t)qg * HD + d] * 0.125f : 0.f;
        qsT[d * 65 + r] = v;
    }
    // rel bias rows for this q tile
#pragma unroll
    for (int it = 0; it < 8; ++it) {
        int idx = tid + it * 256;       // 2048
        int r = idx >> 5, c = idx & 31;
        int qg = q0 + r;
        float hv = 0.f, wv = 0.f;
        if (qg >= NT && qg < NSEQ) {
            int pix = qg - NT;
            int hq = pix >> 5, wq = pix & 31;
            size_t rbase = (((size_t)bh * 32 + hq) * 32 + wq) * 32;
            hv = g_relh[rbase + c];
            wv = g_relw[rbase + c];
        }
        rhs[idx] = hv;
        rws[idx] = wv;
    }
    if (tid < 64) { rowm[tid] = -3.0e38f; rowl[tid] = 0.f; }

    float O[4][4];
#pragma unroll
    for (int i = 0; i < 4; ++i)
#pragma unroll
        for (int j = 0; j < 4; ++j) O[i][j] = 0.f;

    __syncthreads();

    for (int k0 = 0; k0 < NSEQ; k0 += 64) {
        // stage K (transposed) and V (natural)
#pragma unroll
        for (int it = 0; it < 16; ++it) {
            int idx = tid + it * 256;
            int r = idx >> 6, d = idx & 63;
            int kg = k0 + r;
            float kvv = 0.f, vvv = 0.f;
            if (kg < NSEQ) {
                kvv = kbase[(size_t)kg * HD + d];
                vvv = vbase[(size_t)kg * HD + d];
            }
            ksT[d * 65 + r] = kvv;
            vs[r * 64 + d] = vvv;
        }
        __syncthreads();

        // S = Q*scale @ K^T
        float s[4][4];
#pragma unroll
        for (int i = 0; i < 4; ++i)
#pragma unroll
            for (int j = 0; j < 4; ++j) s[i][j] = 0.f;
#pragma unroll 8
        for (int d = 0; d < 64; ++d) {
            float a[4], bb[4];
#pragma unroll
            for (int i = 0; i < 4; ++i) a[i] = qsT[d * 65 + ty * 4 + i];
#pragma unroll
            for (int j = 0; j < 4; ++j) bb[j] = ksT[d * 65 + tx * 4 + j];
#pragma unroll
            for (int i = 0; i < 4; ++i)
#pragma unroll
                for (int j = 0; j < 4; ++j) s[i][j] += a[i] * bb[j];
        }

        // bias + mask, write scores to smem
#pragma unroll
        for (int i = 0; i < 4; ++i) {
            int qr = ty * 4 + i;
            int qg = q0 + qr;
            bool qpix = (qg >= NT);
#pragma unroll
            for (int j = 0; j < 4; ++j) {
                int jg = k0 + tx * 4 + j;
                float val;
                if (jg >= NSEQ) {
                    val = -1e30f;
                } else {
                    val = s[i][j];
                    if (qpix) {
                        if (jg < NT) {
                            val -= 100.f;
                        } else {
                            int pj = jg - NT;
                            val += rhs[qr * 32 + (pj >> 5)] + rws[qr * 32 + (pj & 31)];
                        }
                    }
                }
                ps[qr * 68 + tx * 4 + j] = val;
            }
        }
        __syncthreads();

        // online softmax: 4 threads per row
        {
            int r = tid >> 2, tg = tid & 3;
            float* prow = ps + r * 68 + tg * 16;
            float tm = -3.0e38f;
#pragma unroll
            for (int c = 0; c < 16; ++c) tm = fmaxf(tm, prow[c]);
            tm = fmaxf(tm, __shfl_xor_sync(0xffffffffu, tm, 1));
            tm = fmaxf(tm, __shfl_xor_sync(0xffffffffu, tm, 2));
            float oldm = rowm[r];
            float newm = fmaxf(oldm, tm);
            float sum = 0.f;
#pragma unroll
            for (int c = 0; c < 16; ++c) {
                float p = __expf(prow[c] - newm);
                prow[c] = p;
                sum += p;
            }
            sum += __shfl_xor_sync(0xffffffffu, sum, 1);
            sum += __shfl_xor_sync(0xffffffffu, sum, 2);
            if (tg == 0) {
                float sc = __expf(oldm - newm);
                rowsc[r] = sc;
                rowl[r] = rowl[r] * sc + sum;
                rowm[r] = newm;
            }
        }
        __syncthreads();

        // O = O*scale + P @ V
        float rs4[4];
#pragma unroll
        for (int i = 0; i < 4; ++i) rs4[i] = rowsc[ty * 4 + i];
#pragma unroll
        for (int i = 0; i < 4; ++i)
#pragma unroll
            for (int j = 0; j < 4; ++j) O[i][j] *= rs4[i];
#pragma unroll 8
        for (int k = 0; k < 64; ++k) {
            float p[4], v[4];
#pragma unroll
            for (int i = 0; i < 4; ++i) p[i] = ps[(ty * 4 + i) * 68 + k];
#pragma unroll
            for (int j = 0; j < 4; ++j) v[j] = vs[k * 64 + tx * 4 + j];
#pragma unroll
            for (int i = 0; i < 4; ++i)
#pragma unroll
                for (int j = 0; j < 4; ++j) O[i][j] += p[i] * v[j];
        }
        __syncthreads();
    }

    // normalize + write context in (B, N, C) layout
#pragma unroll
    for (int i = 0; i < 4; ++i) {
        int qr = ty * 4 + i;
        int qg = q0 + qr;
        if (qg >= NSEQ) continue;
        float inv = 1.f / rowl[qr];
        float4 o;
        o.x = O[i][0] * inv; o.y = O[i][1] * inv;
        o.z = O[i][2] * inv; o.w = O[i][3] * inv;
        *(float4*)(g_ctx + ((size_t)b * NSEQ + qg) * C_DIM + head * HD + tx * 4) = o;
    }
}

// ---------------------------------------------------------------------------
// K4: output projection GEMM (8256x768 @ 768x768 + b), writing split output:
// rows with n>=nt -> x_out [0, 6291456), rows n<nt -> vp_out tail.
// ---------------------------------------------------------------------------
__global__ __launch_bounds__(256) void proj_gemm_kernel(
    const float* __restrict__ W, const float* __restrict__ bias,
    float* __restrict__ out)
{
    __shared__ float As[8][128];
    __shared__ float Bs[8][128];

    const int m0 = blockIdx.y * 128;
    const int n0 = blockIdx.x * 128;
    const int tid = threadIdx.x;
    const int tx = tid & 15, ty = tid >> 4;

    const int aRow = tid >> 1;
    const int aK4  = (tid & 1) * 4;
    const int am   = m0 + aRow;
    const bool avalid = (am < MROWS);
    const float* arp = g_ctx + (size_t)(avalid ? am : 0) * C_DIM;

    const int bK = tid >> 5;
    const int bN = (tid & 31) * 4;

    float acc[8][8];
#pragma unroll
    for (int i = 0; i < 8; ++i)
#pragma unroll
        for (int j = 0; j < 8; ++j) acc[i][j] = 0.f;

    for (int k0 = 0; k0 < C_DIM; k0 += 8) {
        float4 av = avalid ? *(const float4*)(arp + k0 + aK4)
                           : make_float4(0.f, 0.f, 0.f, 0.f);
        As[aK4 + 0][aRow] = av.x;
        As[aK4 + 1][aRow] = av.y;
        As[aK4 + 2][aRow] = av.z;
        As[aK4 + 3][aRow] = av.w;
        *(float4*)&Bs[bK][bN] =
            *(const float4*)(W + (size_t)(k0 + bK) * C_DIM + n0 + bN);
        __syncthreads();
#pragma unroll
        for (int k = 0; k < 8; ++k) {
            float a[8], bb[8];
            *(float4*)&a[0]  = *(float4*)&As[k][ty * 8];
            *(float4*)&a[4]  = *(float4*)&As[k][ty * 8 + 4];
            *(float4*)&bb[0] = *(float4*)&Bs[k][tx * 8];
            *(float4*)&bb[4] = *(float4*)&Bs[k][tx * 8 + 4];
#pragma unroll
            for (int i = 0; i < 8; ++i)
#pragma unroll
                for (int j = 0; j < 8; ++j) acc[i][j] += a[i] * bb[j];
        }
        __syncthreads();
    }

    const int ncol = n0 + tx * 8;
    float bb8[8];
#pragma unroll
    for (int j = 0; j < 8; ++j) bb8[j] = bias[ncol + j];

#pragma unroll
    for (int i = 0; i < 8; ++i) {
        int m = m0 + ty * 8 + i;
        if (m >= MROWS) continue;
        int b = m / NSEQ, nn = m % NSEQ;
        float* dst = (nn < NT)
            ? (out + XOUT_ELEMS + ((size_t)b * NT + nn) * C_DIM)
            : (out + ((size_t)b * HW + (nn - NT)) * C_DIM);
        float4 v0, v1;
        v0.x = acc[i][0] + bb8[0]; v0.y = acc[i][1] + bb8[1];
        v0.z = acc[i][2] + bb8[2]; v0.w = acc[i][3] + bb8[3];
        v1.x = acc[i][4] + bb8[4]; v1.y = acc[i][5] + bb8[5];
        v1.z = acc[i][6] + bb8[6]; v1.w = acc[i][7] + bb8[7];
        *(float4*)(dst + ncol) = v0;
        *(float4*)(dst + ncol + 4) = v1;
    }
}

// ---------------------------------------------------------------------------
extern "C" void kernel_launch(void* const* d_in, const int* in_sizes, int n_in,
                              void* d_out, int out_size)
{
    const float* x      = (const float*)d_in[0];
    const float* vp     = (const float*)d_in[1];
    const float* qkv_w  = (const float*)d_in[2];
    const float* qkv_b  = (const float*)d_in[3];
    const float* proj_w = (const float*)d_in[4];
    const float* proj_b = (const float*)d_in[5];
    const float* rph    = (const float*)d_in[6];
    const float* rpw    = (const float*)d_in[7];
    float* out = (float*)d_out;

    (void)in_sizes; (void)n_in; (void)out_size;

    cudaFuncSetAttribute(attn_kernel,
                         cudaFuncAttributeMaxDynamicSharedMemorySize,
                         ATTN_SMEM_BYTES);

    qkv_gemm_kernel<<<dim3(QKV_N / 128, (MROWS + 127) / 128), 256>>>(x, vp, qkv_w, qkv_b);
    rel_kernel<<<dim3(32, BHN, 2), 256>>>(rph, rpw);
    attn_kernel<<<dim3((NSEQ + 63) / 64, BHN), 256, ATTN_SMEM_BYTES>>>();
    proj_gemm_kernel<<<dim3(C_DIM / 128, (MROWS + 127) / 128), 256>>>(proj_w, proj_b, out);
}

// round 4
// speedup vs baseline: 2.0001x; 2.0001x over previous
#include <cuda_runtime.h>

// ---------------------------------------------------------------------------
// PromptedAttention: B=8, H=W=32, C=768, heads=12, hd=64, nt=8, N=1032
// Round 3: tf32 mma.sync tensor-core path (resubmit of R2 — infra failure).
// ---------------------------------------------------------------------------

#define BATCH     8
#define HEADS     12
#define HD        64
#define C_DIM     768
#define NT        8
#define HW        1024
#define NSEQ      1032
#define BHN       96
#define MROWS     8256
#define QKV_N     2304
#define XOUT_ELEMS 6291456

__device__ float g_q[BHN * NSEQ * HD];
__device__ float g_k[BHN * NSEQ * HD];
__device__ float g_v[BHN * NSEQ * HD];
__device__ float g_relh[BHN * 32 * 32 * 32];
__device__ float g_relw[BHN * 32 * 32 * 32];
__device__ float g_ctx[MROWS * C_DIM];

__device__ __forceinline__ unsigned f2tf(float f) {
    unsigned u;
    asm("cvt.rna.tf32.f32 %0, %1;" : "=r"(u) : "f"(f));
    return u;
}
__device__ __forceinline__ float f2tff(float f) { return __uint_as_float(f2tf(f)); }

__device__ __forceinline__ void mma8(float* c, const unsigned* a, const unsigned* b) {
    asm volatile(
        "mma.sync.aligned.m16n8k8.row.col.f32.tf32.tf32.f32 "
        "{%0,%1,%2,%3}, {%4,%5,%6,%7}, {%8,%9}, {%0,%1,%2,%3};\n"
        : "+f"(c[0]), "+f"(c[1]), "+f"(c[2]), "+f"(c[3])
        : "r"(a[0]), "r"(a[1]), "r"(a[2]), "r"(a[3]), "r"(b[0]), "r"(b[1]));
}

// ---------------------------------------------------------------------------
// K1: fused concat + QKV GEMM (tf32 mma). 128x128 tile, BK=16, 8 warps 4x2.
// ---------------------------------------------------------------------------
__global__ __launch_bounds__(256) void qkv_mma_kernel(
    const float* __restrict__ x, const float* __restrict__ vp,
    const float* __restrict__ W, const float* __restrict__ bias)
{
    __shared__ float As[128 * 20];   // [m][k], ld=20 (conflict-free A frags)
    __shared__ float Bs[16 * 136];   // [k][n], ld=136 (conflict-free B frags)

    const int m0 = blockIdx.y * 128;
    const int n0 = blockIdx.x * 128;
    const int tid = threadIdx.x;
    const int wid = tid >> 5, lane = tid & 31;
    const int g = lane >> 2, tig = lane & 3;
    const int wm = wid >> 1, wn = wid & 1;

    const int aRow = tid >> 1;
    const int aK   = (tid & 1) * 8;
    const int am   = m0 + aRow;
    const bool av  = (am < MROWS);
    const float* arp;
    {
        int mm = av ? am : 0;
        int b = mm / NSEQ, n = mm % NSEQ;
        arp = (n < NT) ? (vp + ((size_t)b * NT + n) * C_DIM)
                       : (x  + ((size_t)b * HW + (n - NT)) * C_DIM);
    }
    const int bk = tid >> 5;
    const int bn = (tid & 31) * 4;

    float c[2][8][4];
#pragma unroll
    for (int mt = 0; mt < 2; ++mt)
#pragma unroll
        for (int nt = 0; nt < 8; ++nt)
#pragma unroll
            for (int j = 0; j < 4; ++j) c[mt][nt][j] = 0.f;

    for (int k0 = 0; k0 < C_DIM; k0 += 16) {
#pragma unroll
        for (int i = 0; i < 2; ++i) {
            float4 t = av ? *(const float4*)(arp + k0 + aK + i * 4)
                          : make_float4(0.f, 0.f, 0.f, 0.f);
            float4 o;
            o.x = f2tff(t.x); o.y = f2tff(t.y); o.z = f2tff(t.z); o.w = f2tff(t.w);
            *(float4*)&As[aRow * 20 + aK + i * 4] = o;
        }
#pragma unroll
        for (int i = 0; i < 2; ++i) {
            int kk = bk + i * 8;
            float4 t = *(const float4*)(W + (size_t)(k0 + kk) * QKV_N + n0 + bn);
            float4 o;
            o.x = f2tff(t.x); o.y = f2tff(t.y); o.z = f2tff(t.z); o.w = f2tff(t.w);
            *(float4*)&Bs[kk * 136 + bn] = o;
        }
        __syncthreads();

        const unsigned* Au = (const unsigned*)As;
        const unsigned* Bu = (const unsigned*)Bs;
#pragma unroll
        for (int ks = 0; ks < 2; ++ks) {
            unsigned a[2][4];
#pragma unroll
            for (int mt = 0; mt < 2; ++mt) {
                int mr = wm * 32 + mt * 16;
                a[mt][0] = Au[(mr + g    ) * 20 + ks * 8 + tig];
                a[mt][1] = Au[(mr + g + 8) * 20 + ks * 8 + tig];
                a[mt][2] = Au[(mr + g    ) * 20 + ks * 8 + tig + 4];
                a[mt][3] = Au[(mr + g + 8) * 20 + ks * 8 + tig + 4];
            }
            unsigned b[8][2];
#pragma unroll
            for (int nt = 0; nt < 8; ++nt) {
                int nc = wn * 64 + nt * 8 + g;
                b[nt][0] = Bu[(ks * 8 + tig    ) * 136 + nc];
                b[nt][1] = Bu[(ks * 8 + tig + 4) * 136 + nc];
            }
#pragma unroll
            for (int mt = 0; mt < 2; ++mt)
#pragma unroll
                for (int nt = 0; nt < 8; ++nt) mma8(c[mt][nt], a[mt], b[nt]);
        }
        __syncthreads();
    }

    // epilogue: scatter to g_q/g_k/g_v
    float* bufs[3] = {g_q, g_k, g_v};
#pragma unroll
    for (int nt = 0; nt < 8; ++nt) {
        int col = n0 + wn * 64 + nt * 8 + tig * 2;
        int which = col / C_DIM;
        int c2 = col % C_DIM;
        int head = c2 >> 6, db = c2 & 63;
        float b0v = bias[col], b1v = bias[col + 1];
        float* buf = bufs[which];
#pragma unroll
        for (int mt = 0; mt < 2; ++mt) {
#pragma unroll
            for (int h = 0; h < 2; ++h) {
                int m = m0 + wm * 32 + mt * 16 + g + h * 8;
                if (m >= MROWS) continue;
                int bb = m / NSEQ, nn = m % NSEQ;
                float* dst = buf + (size_t)bb * (HEADS * NSEQ * HD)
                                 + (size_t)head * (NSEQ * HD)
                                 + (size_t)nn * HD + db;
                float2 v;
                v.x = c[mt][nt][h * 2 + 0] + b0v;
                v.y = c[mt][nt][h * 2 + 1] + b1v;
                *(float2*)dst = v;
            }
        }
    }
}

// ---------------------------------------------------------------------------
// K2: rel_h / rel_w bias GEMMs (SIMT fp32, small).
// ---------------------------------------------------------------------------
__global__ __launch_bounds__(256) void rel_kernel(
    const float* __restrict__ rph, const float* __restrict__ rpw)
{
    __shared__ float qs[32 * 64];
    __shared__ float RsT[64 * 33];

    const int bh = blockIdx.y;
    const int idx0 = blockIdx.x;
    const int variant = blockIdx.z;
    const int tid = threadIdx.x;

#pragma unroll
    for (int it = 0; it < 8; ++it) {
        int idx = tid + it * 256;
        int r = idx >> 6, c = idx & 63;
        int n = (variant == 0) ? (NT + idx0 * 32 + r) : (NT + r * 32 + idx0);
        qs[idx] = g_q[((size_t)bh * NSEQ + n) * HD + c];
    }
    const float* rp = (variant == 0) ? rph : rpw;
#pragma unroll
    for (int it = 0; it < 8; ++it) {
        int idx = tid + it * 256;
        int k = idx >> 6, c = idx & 63;
        RsT[c * 33 + k] = rp[(size_t)(idx0 - k + 31) * HD + c];
    }
    __syncthreads();

    const int ty = tid >> 3;
    const int txk = tid & 7;
    float acc[4] = {0.f, 0.f, 0.f, 0.f};
#pragma unroll 8
    for (int c = 0; c < 64; ++c) {
        float q = qs[ty * 64 + c];
#pragma unroll
        for (int j = 0; j < 4; ++j) acc[j] += q * RsT[c * 33 + txk * 4 + j];
    }
    float* outb = (variant == 0) ? g_relh : g_relw;
    size_t base = (variant == 0)
        ? ((((size_t)bh * 32 + idx0) * 32 + ty) * 32)
        : ((((size_t)bh * 32 + ty) * 32 + idx0) * 32);
#pragma unroll
    for (int j = 0; j < 4; ++j) outb[base + txk * 4 + j] = acc[j];
}

// ---------------------------------------------------------------------------
// K3: flash attention with tf32 mma for S and PV; fp32 SIMT online softmax.
// 64-q x 64-key tiles, 8 warps 4(m) x 2(n), warp S-tile 16x32, O-tile 16x32.
// ---------------------------------------------------------------------------
#define ATT_SM_FLOATS (3 * 64 * 68 + 64 * 72 + 2 * 64 * 32 + 3 * 64)
#define ATT_SM_BYTES  (ATT_SM_FLOATS * 4)

__global__ __launch_bounds__(256) void attn_mma_kernel()
{
    extern __shared__ float sm[];
    float* Qs   = sm;                 // [64 q][68], tf32, prescaled
    float* Ks   = Qs + 64 * 68;       // [64 key][68], tf32
    float* ps   = Ks + 64 * 68;       // [64 q][68], S then P(tf32)
    float* Vs   = ps + 64 * 68;       // [64 key][72], tf32
    float* rhs  = Vs + 64 * 72;       // [64 q][32]
    float* rws  = rhs + 64 * 32;      // [64 q][32]
    float* rowm = rws + 64 * 32;
    float* rowl = rowm + 64;
    float* rowsc = rowl + 64;

    const int tid = threadIdx.x;
    const int wid = tid >> 5, lane = tid & 31;
    const int g = lane >> 2, tig = lane & 3;
    const int wm = wid >> 1, wn = wid & 1;
    const int bh = blockIdx.y;
    const int b = bh / HEADS, head = bh % HEADS;
    const int q0 = blockIdx.x * 64;

    const float* qbase = g_q + (size_t)bh * NSEQ * HD;
    const float* kbase = g_k + (size_t)bh * NSEQ * HD;
    const float* vbase = g_v + (size_t)bh * NSEQ * HD;

#pragma unroll
    for (int it = 0; it < 16; ++it) {
        int idx = tid + it * 256;
        int r = idx >> 6, d = idx & 63;
        int qg = q0 + r;
        float v = (qg < NSEQ) ? qbase[(size_t)qg * HD + d] * 0.125f : 0.f;
        Qs[r * 68 + d] = f2tff(v);
    }
#pragma unroll
    for (int it = 0; it < 8; ++it) {
        int idx = tid + it * 256;
        int r = idx >> 5, cc = idx & 31;
        int qg = q0 + r;
        float hv = 0.f, wv = 0.f;
        if (qg >= NT && qg < NSEQ) {
            int pix = qg - NT;
            int hq = pix >> 5, wq = pix & 31;
            size_t rbase = (((size_t)bh * 32 + hq) * 32 + wq) * 32;
            hv = g_relh[rbase + cc];
            wv = g_relw[rbase + cc];
        }
        rhs[idx] = hv;
        rws[idx] = wv;
    }
    if (tid < 64) { rowm[tid] = -3.0e38f; rowl[tid] = 0.f; }

    float oc[4][4];
#pragma unroll
    for (int nt = 0; nt < 4; ++nt)
#pragma unroll
        for (int j = 0; j < 4; ++j) oc[nt][j] = 0.f;

    __syncthreads();

    for (int k0 = 0; k0 < NSEQ; k0 += 64) {
#pragma unroll
        for (int it = 0; it < 16; ++it) {
            int idx = tid + it * 256;
            int r = idx >> 6, d = idx & 63;
            int kg = k0 + r;
            float kv = 0.f, vv = 0.f;
            if (kg < NSEQ) {
                kv = kbase[(size_t)kg * HD + d];
                vv = vbase[(size_t)kg * HD + d];
            }
            Ks[r * 68 + d] = f2tff(kv);
            Vs[r * 72 + d] = f2tff(vv);
        }
        __syncthreads();

        const unsigned* Qu = (const unsigned*)Qs;
        const unsigned* Ku = (const unsigned*)Ks;

        float sc4[4][4];
#pragma unroll
        for (int nt = 0; nt < 4; ++nt)
#pragma unroll
            for (int j = 0; j < 4; ++j) sc4[nt][j] = 0.f;

#pragma unroll
        for (int ks = 0; ks < 8; ++ks) {
            unsigned a[4];
            int mr = wm * 16;
            a[0] = Qu[(mr + g    ) * 68 + ks * 8 + tig];
            a[1] = Qu[(mr + g + 8) * 68 + ks * 8 + tig];
            a[2] = Qu[(mr + g    ) * 68 + ks * 8 + tig + 4];
            a[3] = Qu[(mr + g + 8) * 68 + ks * 8 + tig + 4];
#pragma unroll
            for (int nt = 0; nt < 4; ++nt) {
                unsigned bb[2];
                int key = wn * 32 + nt * 8 + g;
                bb[0] = Ku[key * 68 + ks * 8 + tig];
                bb[1] = Ku[key * 68 + ks * 8 + tig + 4];
                mma8(sc4[nt], a, bb);
            }
        }

        // store raw S tiles
#pragma unroll
        for (int nt = 0; nt < 4; ++nt) {
            int col = wn * 32 + nt * 8 + tig * 2;
            int r0 = wm * 16 + g;
            *(float2*)&ps[r0 * 68 + col] = make_float2(sc4[nt][0], sc4[nt][1]);
            *(float2*)&ps[(r0 + 8) * 68 + col] = make_float2(sc4[nt][2], sc4[nt][3]);
        }
        __syncthreads();

        // online softmax with bias/mask, 4 threads per row
        {
            int r = tid >> 2, tg = tid & 3;
            int qg = q0 + r;
            float vreg[16];
            float tm = -3.0e38f;
#pragma unroll
            for (int cc = 0; cc < 16; ++cc) {
                int cj = tg * 16 + cc;
                int jg = k0 + cj;
                float val = ps[r * 68 + cj];
                if (jg >= NSEQ) {
                    val = -1e30f;
                } else if (qg >= NT) {
                    if (jg < NT) val -= 100.f;
                    else {
                        int pj = jg - NT;
                        val += rhs[r * 32 + (pj >> 5)] + rws[r * 32 + (pj & 31)];
                    }
                }
                vreg[cc] = val;
                tm = fmaxf(tm, val);
            }
            tm = fmaxf(tm, __shfl_xor_sync(0xffffffffu, tm, 1));
            tm = fmaxf(tm, __shfl_xor_sync(0xffffffffu, tm, 2));
            float oldm = rowm[r];
            float newm = fmaxf(oldm, tm);
            float sum = 0.f;
#pragma unroll
            for (int cc = 0; cc < 16; ++cc) {
                float p = __expf(vreg[cc] - newm);
                sum += p;
                ps[r * 68 + tg * 16 + cc] = f2tff(p);
            }
            sum += __shfl_xor_sync(0xffffffffu, sum, 1);
            sum += __shfl_xor_sync(0xffffffffu, sum, 2);
            if (tg == 0) {
                float s = __expf(oldm - newm);
                rowsc[r] = s;
                rowl[r] = rowl[r] * s + sum;
                rowm[r] = newm;
            }
        }
        __syncthreads();

        // rescale O, then O += P @ V
        const unsigned* pu = (const unsigned*)ps;
        const unsigned* Vu = (const unsigned*)Vs;
        float s0 = rowsc[wm * 16 + g], s1 = rowsc[wm * 16 + g + 8];
#pragma unroll
        for (int nt = 0; nt < 4; ++nt) {
            oc[nt][0] *= s0; oc[nt][1] *= s0;
            oc[nt][2] *= s1; oc[nt][3] *= s1;
        }
#pragma unroll
        for (int ks = 0; ks < 8; ++ks) {
            unsigned a[4];
            int mr = wm * 16;
            a[0] = pu[(mr + g    ) * 68 + ks * 8 + tig];
            a[1] = pu[(mr + g + 8) * 68 + ks * 8 + tig];
            a[2] = pu[(mr + g    ) * 68 + ks * 8 + tig + 4];
            a[3] = pu[(mr + g + 8) * 68 + ks * 8 + tig + 4];
#pragma unroll
            for (int nt = 0; nt < 4; ++nt) {
                unsigned bb[2];
                int dcol = wn * 32 + nt * 8 + g;
                bb[0] = Vu[(ks * 8 + tig    ) * 72 + dcol];
                bb[1] = Vu[(ks * 8 + tig + 4) * 72 + dcol];
                mma8(oc[nt], a, bb);
            }
        }
        __syncthreads();
    }

    // normalize + write context
    {
        int r0 = wm * 16 + g, r1 = r0 + 8;
        int qg0 = q0 + r0, qg1 = q0 + r1;
        float inv0 = (qg0 < NSEQ) ? (1.f / rowl[r0]) : 0.f;
        float inv1 = (qg1 < NSEQ) ? (1.f / rowl[r1]) : 0.f;
#pragma unroll
        for (int nt = 0; nt < 4; ++nt) {
            int col = wn * 32 + nt * 8 + tig * 2;
            if (qg0 < NSEQ) {
                float2 v = make_float2(oc[nt][0] * inv0, oc[nt][1] * inv0);
                *(float2*)(g_ctx + ((size_t)b * NSEQ + qg0) * C_DIM + head * HD + col) = v;
            }
            if (qg1 < NSEQ) {
                float2 v = make_float2(oc[nt][2] * inv1, oc[nt][3] * inv1);
                *(float2*)(g_ctx + ((size_t)b * NSEQ + qg1) * C_DIM + head * HD + col) = v;
            }
        }
    }
}

// ---------------------------------------------------------------------------
// K4: output projection GEMM (tf32 mma), split output write.
// ---------------------------------------------------------------------------
__global__ __launch_bounds__(256) void proj_mma_kernel(
    const float* __restrict__ W, const float* __restrict__ bias,
    float* __restrict__ out)
{
    __shared__ float As[128 * 20];
    __shared__ float Bs[16 * 136];

    const int m0 = blockIdx.y * 128;
    const int n0 = blockIdx.x * 128;
    const int tid = threadIdx.x;
    const int wid = tid >> 5, lane = tid & 31;
    const int g = lane >> 2, tig = lane & 3;
    const int wm = wid >> 1, wn = wid & 1;

    const int aRow = tid >> 1;
    const int aK   = (tid & 1) * 8;
    const int am   = m0 + aRow;
    const bool av  = (am < MROWS);
    const float* arp = g_ctx + (size_t)(av ? am : 0) * C_DIM;

    const int bk = tid >> 5;
    const int bn = (tid & 31) * 4;

    float c[2][8][4];
#pragma unroll
    for (int mt = 0; mt < 2; ++mt)
#pragma unroll
        for (int nt = 0; nt < 8; ++nt)
#pragma unroll
            for (int j = 0; j < 4; ++j) c[mt][nt][j] = 0.f;

    for (int k0 = 0; k0 < C_DIM; k0 += 16) {
#pragma unroll
        for (int i = 0; i < 2; ++i) {
            float4 t = av ? *(const float4*)(arp + k0 + aK + i * 4)
                          : make_float4(0.f, 0.f, 0.f, 0.f);
            float4 o;
            o.x = f2tff(t.x); o.y = f2tff(t.y); o.z = f2tff(t.z); o.w = f2tff(t.w);
            *(float4*)&As[aRow * 20 + aK + i * 4] = o;
        }
#pragma unroll
        for (int i = 0; i < 2; ++i) {
            int kk = bk + i * 8;
            float4 t = *(const float4*)(W + (size_t)(k0 + kk) * C_DIM + n0 + bn);
            float4 o;
            o.x = f2tff(t.x); o.y = f2tff(t.y); o.z = f2tff(t.z); o.w = f2tff(t.w);
            *(float4*)&Bs[kk * 136 + bn] = o;
        }
        __syncthreads();

        const unsigned* Au = (const unsigned*)As;
        const unsigned* Bu = (const unsigned*)Bs;
#pragma unroll
        for (int ks = 0; ks < 2; ++ks) {
            unsigned a[2][4];
#pragma unroll
            for (int mt = 0; mt < 2; ++mt) {
                int mr = wm * 32 + mt * 16;
                a[mt][0] = Au[(mr + g    ) * 20 + ks * 8 + tig];
                a[mt][1] = Au[(mr + g + 8) * 20 + ks * 8 + tig];
                a[mt][2] = Au[(mr + g    ) * 20 + ks * 8 + tig + 4];
                a[mt][3] = Au[(mr + g + 8) * 20 + ks * 8 + tig + 4];
            }
            unsigned b[8][2];
#pragma unroll
            for (int nt = 0; nt < 8; ++nt) {
                int nc = wn * 64 + nt * 8 + g;
                b[nt][0] = Bu[(ks * 8 + tig    ) * 136 + nc];
                b[nt][1] = Bu[(ks * 8 + tig + 4) * 136 + nc];
            }
#pragma unroll
            for (int mt = 0; mt < 2; ++mt)
#pragma unroll
                for (int nt = 0; nt < 8; ++nt) mma8(c[mt][nt], a[mt], b[nt]);
        }
        __syncthreads();
    }

#pragma unroll
    for (int nt = 0; nt < 8; ++nt) {
        int col = n0 + wn * 64 + nt * 8 + tig * 2;
        float b0v = bias[col], b1v = bias[col + 1];
#pragma unroll
        for (int mt = 0; mt < 2; ++mt) {
#pragma unroll
            for (int h = 0; h < 2; ++h) {
                int m = m0 + wm * 32 + mt * 16 + g + h * 8;
                if (m >= MROWS) continue;
                int bb = m / NSEQ, nn = m % NSEQ;
                float* dst = (nn < NT)
                    ? (out + XOUT_ELEMS + ((size_t)bb * NT + nn) * C_DIM)
                    : (out + ((size_t)bb * HW + (nn - NT)) * C_DIM);
                float2 v;
                v.x = c[mt][nt][h * 2 + 0] + b0v;
                v.y = c[mt][nt][h * 2 + 1] + b1v;
                *(float2*)(dst + col) = v;
            }
        }
    }
}

// ---------------------------------------------------------------------------
extern "C" void kernel_launch(void* const* d_in, const int* in_sizes, int n_in,
                              void* d_out, int out_size)
{
    const float* x      = (const float*)d_in[0];
    const float* vp     = (const float*)d_in[1];
    const float* qkv_w  = (const float*)d_in[2];
    const float* qkv_b  = (const float*)d_in[3];
    const float* proj_w = (const float*)d_in[4];
    const float* proj_b = (const float*)d_in[5];
    const float* rph    = (const float*)d_in[6];
    const float* rpw    = (const float*)d_in[7];
    float* out = (float*)d_out;

    (void)in_sizes; (void)n_in; (void)out_size;

    cudaFuncSetAttribute(attn_mma_kernel,
                         cudaFuncAttributeMaxDynamicSharedMemorySize,
                         ATT_SM_BYTES);

    qkv_mma_kernel<<<dim3(QKV_N / 128, (MROWS + 127) / 128), 256>>>(x, vp, qkv_w, qkv_b);
    rel_kernel<<<dim3(32, BHN, 2), 256>>>(rph, rpw);
    attn_mma_kernel<<<dim3((NSEQ + 63) / 64, BHN), 256, ATT_SM_BYTES>>>();
    proj_mma_kernel<<<dim3(C_DIM / 128, (MROWS + 127) / 128), 256>>>(proj_w, proj_b, out);
}